// round 9
// baseline (speedup 1.0000x reference)
#include <cuda_runtime.h>
#include <cstdint>

#define NB   8
#define CH   16
#define LEN  1024
#define DD   7
#define SZ   112
#define HH   16
#define NH   (NB*HH)      // 128
#define DPAD 8

typedef unsigned long long u64;
typedef unsigned int u32;

// Scratch
__device__ float g_q[NH * LEN * DPAD];
__device__ float g_k[NH * LEN * DPAD];
__device__ float g_v[NH * LEN * DPAD];
__device__ u64   g_w2[3 * 56 * SZ];

// ---- f32x2 helpers ----
__device__ __forceinline__ u64 pack2(float lo, float hi) {
    u64 r; asm("mov.b64 %0,{%1,%2};" : "=l"(r) : "f"(lo), "f"(hi)); return r;
}
__device__ __forceinline__ void unpack2(u64 v, float& lo, float& hi) {
    asm("mov.b64 {%0,%1},%2;" : "=f"(lo), "=f"(hi) : "l"(v));
}
__device__ __forceinline__ u64 fma2(u64 a, u64 b, u64 c) {
    u64 d; asm("fma.rn.f32x2 %0,%1,%2,%3;" : "=l"(d) : "l"(a), "l"(b), "l"(c)); return d;
}
__device__ __forceinline__ u64 mul2(u64 a, u64 b) {
    u64 d; asm("mul.rn.f32x2 %0,%1,%2;" : "=l"(d) : "l"(a), "l"(b)); return d;
}
__device__ __forceinline__ u32 cvt_tf32(float f) {
    u32 r; asm("cvt.rna.tf32.f32 %0, %1;" : "=r"(r) : "f"(f)); return r;
}

// ---------------------------------------------------------------------------
// Kernel 0: pack W into [k2][j] u64 table
// ---------------------------------------------------------------------------
__global__ void prep_kernel(const float* __restrict__ Wq,
                            const float* __restrict__ Wk,
                            const float* __restrict__ Wv)
{
    int i = blockIdx.x * 256 + threadIdx.x;
    if (i >= 3 * 56 * SZ) return;
    int m   = i / (56 * SZ);
    int rem = i - m * 56 * SZ;
    int k2  = rem / SZ;
    int j   = rem - k2 * SZ;
    const float* W = (m == 0) ? Wq : (m == 1) ? Wk : Wv;
    g_w2[i] = *reinterpret_cast<const u64*>(W + j * SZ + 2 * k2);
}

// ---------------------------------------------------------------------------
// Kernel 1: QKV projection (k-packed f32x2) — unchanged
// ---------------------------------------------------------------------------
#define PROJ_ROWS 32
#define PTHREADS  224
#define PROJ_SMEM (56 * SZ * 8 + PROJ_ROWS * SZ * 4)

__global__ __launch_bounds__(PTHREADS, 3)
void proj_kernel(const float* __restrict__ x,
                 const float* __restrict__ bq,
                 const float* __restrict__ bk,
                 const float* __restrict__ bv)
{
    extern __shared__ char smraw[];
    u64*   Wt2 = reinterpret_cast<u64*>(smraw);                  // [56][112]
    float* xs  = reinterpret_cast<float*>(smraw + 56 * SZ * 8);  // [32][112]

    const int m = blockIdx.y;
    const float* b = (m == 0) ? bq : (m == 1) ? bk : bv;
    float* dst     = (m == 0) ? g_q : (m == 1) ? g_k : g_v;

    const int t = threadIdx.x;

    const u64* wsrc = g_w2 + m * 56 * SZ;
    #pragma unroll
    for (int i = 0; i < 28; i++) Wt2[i * PTHREADS + t] = wsrc[i * PTHREADS + t];

    const int base = blockIdx.x * PROJ_ROWS;
    #pragma unroll
    for (int it = 0; it < 16; it++) {
        int i = it * PTHREADS + t;
        int r = i / SZ, c = i - r * SZ;
        int row = base + r;
        int n = row >> 10, l = row & 1023;
        xs[r * SZ + c] = x[((n * CH + c / DD) * LEN + l) * DD + (c % DD)];
    }
    __syncthreads();

    const int jt = t % 28, rt = t / 28;
    const int j0 = jt * 4, r0 = rt * 4;

    u64 acc[4][4];
    #pragma unroll
    for (int rr = 0; rr < 4; rr++)
        #pragma unroll
        for (int jj = 0; jj < 4; jj++) acc[rr][jj] = 0ull;

    #pragma unroll 4
    for (int k2 = 0; k2 < 56; k2++) {
        ulonglong2 wA = *reinterpret_cast<const ulonglong2*>(Wt2 + k2 * SZ + j0);
        ulonglong2 wB = *reinterpret_cast<const ulonglong2*>(Wt2 + k2 * SZ + j0 + 2);
        #pragma unroll
        for (int rr = 0; rr < 4; rr++) {
            u64 xv = *reinterpret_cast<const u64*>(xs + (r0 + rr) * SZ + 2 * k2);
            acc[rr][0] = fma2(xv, wA.x, acc[rr][0]);
            acc[rr][1] = fma2(xv, wA.y, acc[rr][1]);
            acc[rr][2] = fma2(xv, wB.x, acc[rr][2]);
            acc[rr][3] = fma2(xv, wB.y, acc[rr][3]);
        }
    }

    #pragma unroll
    for (int rr = 0; rr < 4; rr++) {
        int row = base + r0 + rr;
        int n = row >> 10, l = row & 1023;
        #pragma unroll
        for (int jj = 0; jj < 4; jj++) {
            int j = j0 + jj;
            float lo, hi; unpack2(acc[rr][jj], lo, hi);
            float y = lo + hi + b[j];
            int h = j / DD, dd = j - h * DD;
            dst[((n * HH + h) * LEN + l) * DPAD + dd] = y;
        }
    }
}

// ---------------------------------------------------------------------------
// Kernel 2: hybrid attention.
// Warp = 16 queries x 1024 keys (128 tiles of 8 keys).
// QK+exp exact fp32 (key-pair packed f32x2, scores computed directly in
// mma fragment lanes). PV + ssum via mma.sync m16n8k8 tf32; V fragment has
// a ones-column at n=7 so C[:,7] = softmax denominator.
// CTA: 256 threads (8 warps = 128 queries), grid (128 heads, 8 q-splits).
// smem 64KB: K pair-packed 32KB + V fragments 32KB -> 3 CTAs/SM.
// ---------------------------------------------------------------------------
#define ATHR   256
#define K_OFF  0
#define V_OFF  32768
#define ATTN_SMEM 65536

__global__ __launch_bounds__(ATHR, 3)
void attn_kernel(float* __restrict__ out)
{
    extern __shared__ char sm[];
    const int tid = threadIdx.x;
    const int nh  = blockIdx.x;

    // ---- stage K: pair-packed layout.
    // kp[tile t][pair p=0..3][d] = { K[8t+p][d], K[8t+p+4][d] }  (u64), d=0..6.
    // row stride 64B per pair, 256B per tile.
    {
        #pragma unroll
        for (int it = 0; it < 4; it++) {
            int j = it * ATHR + tid;                 // key row 0..1023
            const float4* src = reinterpret_cast<const float4*>(
                g_k + ((size_t)nh * LEN + j) * DPAD);
            float4 k0 = src[0], k1 = src[1];
            int t = j >> 3, tg = j & 7;
            char* base = sm + K_OFF + t * 256 + (tg & 3) * 64 + ((tg >> 2) << 2);
            *reinterpret_cast<float*>(base +  0) = k0.x;
            *reinterpret_cast<float*>(base +  8) = k0.y;
            *reinterpret_cast<float*>(base + 16) = k0.z;
            *reinterpret_cast<float*>(base + 24) = k0.w;
            *reinterpret_cast<float*>(base + 32) = k1.x;
            *reinterpret_cast<float*>(base + 40) = k1.y;
            *reinterpret_cast<float*>(base + 48) = k1.z;   // d6; d7 slot unused
        }
    }
    // ---- stage V fragments (tf32, B-fragment order for m16n8k8.col):
    // vfrag[t][lane] = { tf32(V[8t+tg][g]), tf32(V[8t+tg+4][g]) }, g=lane>>2
    // g==7 -> ones column (ssum).
    {
        #pragma unroll
        for (int it = 0; it < 16; it++) {
            int e = it * ATHR + tid;                 // 0..4095
            int t = e >> 5, ln = e & 31;
            int tg = ln & 3, g = ln >> 2;
            float v0, v1;
            if (g == 7) { v0 = 1.0f; v1 = 1.0f; }
            else {
                const float* vb = g_v + ((size_t)nh * LEN + t * 8 + tg) * DPAD + g;
                v0 = vb[0];
                v1 = vb[4 * DPAD];
            }
            u64 pk = ((u64)cvt_tf32(v1) << 32) | (u64)cvt_tf32(v0);
            *reinterpret_cast<u64*>(sm + V_OFF + t * 256 + ln * 8) = pk;
        }
    }

    // ---- per-thread query setup ----
    const int w    = tid >> 5;
    const int lane = tid & 31;
    const int g    = lane >> 2;      // 0..7
    const int tg   = lane & 3;       // 0..3
    const int qb   = blockIdx.y * 128 + w * 16;
    const float SC = 1.4426950408889634f / 32.0f;   // log2(e)/sqrt(L)

    u64 qg[7], qh[7];                // broadcast-packed q rows g, g+8
    {
        const float* qA = g_q + ((size_t)nh * LEN + qb + g) * DPAD;
        const float* qB = qA + 8 * DPAD;
        #pragma unroll
        for (int d = 0; d < 7; d++) {
            float a = qA[d] * SC; qg[d] = pack2(a, a);
            float b = qB[d] * SC; qh[d] = pack2(b, b);
        }
    }
    __syncthreads();

    float c0 = 0.f, c1 = 0.f, c2 = 0.f, c3 = 0.f;
    const char* kp = sm + K_OFF + tg * 64;
    const char* vp = sm + V_OFF + lane * 8;

    #pragma unroll 4
    for (int t = 0; t < 128; t++) {
        const ulonglong2 p01 = *reinterpret_cast<const ulonglong2*>(kp);        // d0,d1
        const ulonglong2 p23 = *reinterpret_cast<const ulonglong2*>(kp + 16);   // d2,d3
        const ulonglong2 p45 = *reinterpret_cast<const ulonglong2*>(kp + 32);   // d4,d5
        const u64        p6  = *reinterpret_cast<const u64*>(kp + 48);          // d6

        u64 sA = mul2(qg[0], p01.x);          // -> {s(g,tg), s(g,tg+4)}
        sA = fma2(qg[1], p01.y, sA);
        sA = fma2(qg[2], p23.x, sA);
        sA = fma2(qg[3], p23.y, sA);
        sA = fma2(qg[4], p45.x, sA);
        sA = fma2(qg[5], p45.y, sA);
        sA = fma2(qg[6], p6,   sA);
        u64 sB = mul2(qh[0], p01.x);          // -> {s(g+8,tg), s(g+8,tg+4)}
        sB = fma2(qh[1], p01.y, sB);
        sB = fma2(qh[2], p23.x, sB);
        sB = fma2(qh[3], p23.y, sB);
        sB = fma2(qh[4], p45.x, sB);
        sB = fma2(qh[5], p45.y, sB);
        sB = fma2(qh[6], p6,   sB);

        float sA0, sA1, sB0, sB1;
        unpack2(sA, sA0, sA1);
        unpack2(sB, sB0, sB1);
        float eA0, eA1, eB0, eB1;
        asm("ex2.approx.ftz.f32 %0,%1;" : "=f"(eA0) : "f"(sA0));
        asm("ex2.approx.ftz.f32 %0,%1;" : "=f"(eA1) : "f"(sA1));
        asm("ex2.approx.ftz.f32 %0,%1;" : "=f"(eB0) : "f"(sB0));
        asm("ex2.approx.ftz.f32 %0,%1;" : "=f"(eB1) : "f"(sB1));

        // A fragment: a0=(g,tg) a1=(g+8,tg) a2=(g,tg+4) a3=(g+8,tg+4)
        u32 a0 = cvt_tf32(eA0);
        u32 a1 = cvt_tf32(eB0);
        u32 a2 = cvt_tf32(eA1);
        u32 a3 = cvt_tf32(eB1);

        u32 b0, b1;
        asm("ld.shared.v2.u32 {%0,%1}, [%2];" : "=r"(b0), "=r"(b1) : "r"((u32)__cvta_generic_to_shared(vp)));

        asm("mma.sync.aligned.m16n8k8.row.col.f32.tf32.tf32.f32 "
            "{%0,%1,%2,%3}, {%4,%5,%6,%7}, {%8,%9}, {%0,%1,%2,%3};"
            : "+f"(c0), "+f"(c1), "+f"(c2), "+f"(c3)
            : "r"(a0), "r"(a1), "r"(a2), "r"(a3), "r"(b0), "r"(b1));

        kp += 256;
        vp += 256;
    }

    // ---- epilogue: C rows g, g+8; cols 2tg, 2tg+1 (col 7 = ssum) ----
    float sg = __shfl_sync(0xffffffffu, c1, lane | 3);
    float sh = __shfl_sync(0xffffffffu, c3, lane | 3);
    float ig = 1.0f / sg;
    float ih = 1.0f / sh;

    float* o0 = out + ((size_t)nh * LEN + qb + g) * DD;
    float* o1 = o0 + 8 * DD;
    if (tg < 3) {
        o0[2 * tg]     = c0 * ig;
        o0[2 * tg + 1] = c1 * ig;
        o1[2 * tg]     = c2 * ih;
        o1[2 * tg + 1] = c3 * ih;
    } else {
        o0[6] = c0 * ig;
        o1[6] = c2 * ih;
    }
}

// ---------------------------------------------------------------------------
extern "C" void kernel_launch(void* const* d_in, const int* in_sizes, int n_in,
                              void* d_out, int out_size)
{
    const float* x  = (const float*)d_in[0];
    const float* Wq = (const float*)d_in[1];
    const float* bq = (const float*)d_in[2];
    const float* Wk = (const float*)d_in[3];
    const float* bk = (const float*)d_in[4];
    const float* Wv = (const float*)d_in[5];
    const float* bv = (const float*)d_in[6];
    float* out = (float*)d_out;

    cudaFuncSetAttribute(proj_kernel, cudaFuncAttributeMaxDynamicSharedMemorySize, PROJ_SMEM);
    cudaFuncSetAttribute(attn_kernel, cudaFuncAttributeMaxDynamicSharedMemorySize, ATTN_SMEM);

    prep_kernel<<<(3 * 56 * SZ + 255) / 256, 256>>>(Wq, Wk, Wv);

    dim3 pgrid((NB * LEN) / PROJ_ROWS, 3);       // 256 x 3
    proj_kernel<<<pgrid, PTHREADS, PROJ_SMEM>>>(x, bq, bk, bv);

    dim3 agrid(NH, 8);                           // 128 x 8 = 1024 CTAs
    attn_kernel<<<agrid, ATHR, ATTN_SMEM>>>(out);
}

// round 10
// speedup vs baseline: 1.0524x; 1.0524x over previous
#include <cuda_runtime.h>
#include <cstdint>

#define NB   8
#define CH   16
#define LEN  1024
#define DD   7
#define SZ   112
#define HH   16
#define NH   (NB*HH)      // 128
#define DPAD 8

typedef unsigned long long u64;
typedef unsigned int u32;

// Scratch
__device__ float g_q[NH * LEN * DPAD];            // [nh][l][8] f32
__device__ u64   g_kp[NH * 512 * 8];              // key-pair packed: [nh][jp][d] = {K[2jp][d],K[2jp+1][d]}
__device__ u32   g_vfrag[NH * 64 * 32 * 2];       // bf16 B-fragments: [nh][t][ln][half]
__device__ u64   g_w2[3 * 56 * SZ];

#define ONES_BF16X4 0x3F803F803F803F80ull

// ---- f32x2 helpers ----
__device__ __forceinline__ u64 pack2(float lo, float hi) {
    u64 r; asm("mov.b64 %0,{%1,%2};" : "=l"(r) : "f"(lo), "f"(hi)); return r;
}
__device__ __forceinline__ void unpack2(u64 v, float& lo, float& hi) {
    asm("mov.b64 {%0,%1},%2;" : "=f"(lo), "=f"(hi) : "l"(v));
}
__device__ __forceinline__ u64 fma2(u64 a, u64 b, u64 c) {
    u64 d; asm("fma.rn.f32x2 %0,%1,%2,%3;" : "=l"(d) : "l"(a), "l"(b), "l"(c)); return d;
}
__device__ __forceinline__ u64 mul2(u64 a, u64 b) {
    u64 d; asm("mul.rn.f32x2 %0,%1,%2;" : "=l"(d) : "l"(a), "l"(b)); return d;
}
__device__ __forceinline__ u32 bf16x2_of(float lo, float hi) {
    u32 r; asm("cvt.rn.bf16x2.f32 %0,%1,%2;" : "=r"(r) : "f"(hi), "f"(lo)); return r;
}

// ---------------------------------------------------------------------------
// Kernel 0: pack W into [k2][j] u64 table
// ---------------------------------------------------------------------------
__global__ void prep_kernel(const float* __restrict__ Wq,
                            const float* __restrict__ Wk,
                            const float* __restrict__ Wv)
{
    int i = blockIdx.x * 256 + threadIdx.x;
    if (i >= 3 * 56 * SZ) return;
    int m   = i / (56 * SZ);
    int rem = i - m * 56 * SZ;
    int k2  = rem / SZ;
    int j   = rem - k2 * SZ;
    const float* W = (m == 0) ? Wq : (m == 1) ? Wk : Wv;
    g_w2[i] = *reinterpret_cast<const u64*>(W + j * SZ + 2 * k2);
}

// ---------------------------------------------------------------------------
// Kernel 1: QKV projection. Q -> [nh][l][8] f32; K -> key-pair u64 layout;
// V -> bf16 mma B-fragments. Each thread owns 4 consecutive rows (4-aligned),
// so both rows of each (even,odd) pair are in registers.
// ---------------------------------------------------------------------------
#define PROJ_ROWS 32
#define PTHREADS  224
#define PROJ_SMEM (56 * SZ * 8 + PROJ_ROWS * SZ * 4)

__global__ __launch_bounds__(PTHREADS, 3)
void proj_kernel(const float* __restrict__ x,
                 const float* __restrict__ bq,
                 const float* __restrict__ bk,
                 const float* __restrict__ bv)
{
    extern __shared__ char smraw[];
    u64*   Wt2 = reinterpret_cast<u64*>(smraw);                  // [56][112]
    float* xs  = reinterpret_cast<float*>(smraw + 56 * SZ * 8);  // [32][112]

    const int m = blockIdx.y;
    const float* b = (m == 0) ? bq : (m == 1) ? bk : bv;

    const int t = threadIdx.x;

    const u64* wsrc = g_w2 + m * 56 * SZ;
    #pragma unroll
    for (int i = 0; i < 28; i++) Wt2[i * PTHREADS + t] = wsrc[i * PTHREADS + t];

    const int base = blockIdx.x * PROJ_ROWS;
    #pragma unroll
    for (int it = 0; it < 16; it++) {
        int i = it * PTHREADS + t;
        int r = i / SZ, c = i - r * SZ;
        int row = base + r;
        int n = row >> 10, l = row & 1023;
        xs[r * SZ + c] = x[((n * CH + c / DD) * LEN + l) * DD + (c % DD)];
    }
    __syncthreads();

    const int jt = t % 28, rt = t / 28;
    const int j0 = jt * 4, r0 = rt * 4;

    u64 acc[4][4];
    #pragma unroll
    for (int rr = 0; rr < 4; rr++)
        #pragma unroll
        for (int jj = 0; jj < 4; jj++) acc[rr][jj] = 0ull;

    #pragma unroll 4
    for (int k2 = 0; k2 < 56; k2++) {
        ulonglong2 wA = *reinterpret_cast<const ulonglong2*>(Wt2 + k2 * SZ + j0);
        ulonglong2 wB = *reinterpret_cast<const ulonglong2*>(Wt2 + k2 * SZ + j0 + 2);
        #pragma unroll
        for (int rr = 0; rr < 4; rr++) {
            u64 xv = *reinterpret_cast<const u64*>(xs + (r0 + rr) * SZ + 2 * k2);
            acc[rr][0] = fma2(xv, wA.x, acc[rr][0]);
            acc[rr][1] = fma2(xv, wA.y, acc[rr][1]);
            acc[rr][2] = fma2(xv, wB.x, acc[rr][2]);
            acc[rr][3] = fma2(xv, wB.y, acc[rr][3]);
        }
    }

    const int row0 = base + r0;          // 4-aligned; all 4 rows same n
    const int n  = row0 >> 10;
    const int l0 = row0 & 1023;

    #pragma unroll
    for (int jj = 0; jj < 4; jj++) {
        int j = j0 + jj;
        int h = j / DD, dd = j - h * DD;
        int nhh = n * HH + h;
        float y[4];
        #pragma unroll
        for (int rr = 0; rr < 4; rr++) {
            float lo, hi; unpack2(acc[rr][jj], lo, hi);
            y[rr] = lo + hi + b[j];
        }
        if (m == 0) {
            float* dq = g_q + ((size_t)nhh * LEN + l0) * DPAD + dd;
            dq[0] = y[0]; dq[DPAD] = y[1]; dq[2 * DPAD] = y[2]; dq[3 * DPAD] = y[3];
        } else if (m == 1) {
            u64* dk = g_kp + ((size_t)nhh * 512 + (l0 >> 1)) * 8 + dd;
            dk[0] = pack2(y[0], y[1]);
            dk[8] = pack2(y[2], y[3]);
        } else {
            u32 v01 = bf16x2_of(y[0], y[1]);
            u32 v23 = bf16x2_of(y[2], y[3]);
            int tt  = l0 >> 4;
            int pp0 = l0 & 15;           // 0,4,8,12
            int pp1 = pp0 + 2;
            int half0 = pp0 >> 3, tg0 = (pp0 & 7) >> 1;
            int half1 = pp1 >> 3, tg1 = (pp1 & 7) >> 1;
            u32* dv = g_vfrag + ((size_t)nhh * 64 + tt) * 64;
            dv[(dd * 4 + tg0) * 2 + half0] = v01;
            dv[(dd * 4 + tg1) * 2 + half1] = v23;
        }
    }
}

// ---------------------------------------------------------------------------
// Kernel 2: attention. Warp = 16 queries x 1024 keys (64 k16-tiles).
// QK + exp exact fp32 (key-pair f32x2, scores land directly in mma A-fragment
// lanes). PV + ssum via native bf16 mma.sync m16n8k16; V B-fragment has a
// ones-column at n=7 so C[:,7] = softmax denominator.
// CTA: 128 thr (4 warps = 64 queries). Grid (128 heads, 16 q-splits).
// smem: K pairs 32KB + V fragments 16KB = 48KB -> 4 CTAs/SM.
// ---------------------------------------------------------------------------
#define ATHR   128
#define K_OFF  0
#define V_OFF  32768
#define ATTN_SMEM 49152

__global__ __launch_bounds__(ATHR, 4)
void attn_kernel(float* __restrict__ out)
{
    extern __shared__ char sm[];
    const int tid = threadIdx.x;
    const int nh  = blockIdx.x;

    // ---- stage K pairs (coalesced u128 copy) ----
    {
        const ulonglong2* src = reinterpret_cast<const ulonglong2*>(g_kp + (size_t)nh * 512 * 8);
        ulonglong2* dst = reinterpret_cast<ulonglong2*>(sm + K_OFF);
        #pragma unroll
        for (int i = 0; i < 16; i++)
            dst[i * ATHR + tid] = src[i * ATHR + tid];
    }
    // ---- stage V fragments (coalesced u64 copy; ones column for ln>=28) ----
    {
        const u64* src = reinterpret_cast<const u64*>(g_vfrag) + (size_t)nh * 2048;
        u64* dst = reinterpret_cast<u64*>(sm + V_OFF);
        #pragma unroll
        for (int i = 0; i < 16; i++) {
            int idx = i * ATHR + tid;
            u64 v = ((idx & 31) >= 28) ? ONES_BF16X4 : src[idx];
            dst[idx] = v;
        }
    }

    // ---- per-thread query setup ----
    const int w    = tid >> 5;
    const int lane = tid & 31;
    const int g    = lane >> 2;      // groupID 0..7
    const int tg   = lane & 3;       // thread-in-group
    const int qb   = blockIdx.y * 64 + w * 16;
    const float SC = 1.4426950408889634f / 32.0f;   // log2(e)/sqrt(L)

    u64 qg[7], qh[7];                // broadcast-packed q rows g, g+8
    {
        const float* qA = g_q + ((size_t)nh * LEN + qb + g) * DPAD;
        const float* qB = qA + 8 * DPAD;
        #pragma unroll
        for (int d = 0; d < 7; d++) {
            float a = qA[d] * SC; qg[d] = pack2(a, a);
            float b = qB[d] * SC; qh[d] = pack2(b, b);
        }
    }
    __syncthreads();

    float c0 = 0.f, c1 = 0.f, c2 = 0.f, c3 = 0.f;
    const char* kp = sm + K_OFF + tg * 64;          // pair jp = 8t + tg
    const char* vp = sm + V_OFF + lane * 8;

    #pragma unroll 2
    for (int t = 0; t < 64; t++) {
        // chain 0/2 pairs: jp = 8t+tg (keys 16t+2tg, +1)
        const ulonglong2 A0 = *reinterpret_cast<const ulonglong2*>(kp);
        const ulonglong2 A1 = *reinterpret_cast<const ulonglong2*>(kp + 16);
        const ulonglong2 A2 = *reinterpret_cast<const ulonglong2*>(kp + 32);
        const u64        A3 = *reinterpret_cast<const u64*>(kp + 48);
        // chain 1/3 pairs: jp = 8t+4+tg (keys 16t+8+2tg, +1)
        const ulonglong2 B0 = *reinterpret_cast<const ulonglong2*>(kp + 256);
        const ulonglong2 B1 = *reinterpret_cast<const ulonglong2*>(kp + 272);
        const ulonglong2 B2 = *reinterpret_cast<const ulonglong2*>(kp + 288);
        const u64        B3 = *reinterpret_cast<const u64*>(kp + 304);

        u64 sA0 = mul2(qg[0], A0.x);    // row g,   k-lo pair
        u64 sA1 = mul2(qg[0], B0.x);    // row g,   k-hi pair
        u64 sB0 = mul2(qh[0], A0.x);    // row g+8, k-lo
        u64 sB1 = mul2(qh[0], B0.x);    // row g+8, k-hi
        sA0 = fma2(qg[1], A0.y, sA0);  sA1 = fma2(qg[1], B0.y, sA1);
        sB0 = fma2(qh[1], A0.y, sB0);  sB1 = fma2(qh[1], B0.y, sB1);
        sA0 = fma2(qg[2], A1.x, sA0);  sA1 = fma2(qg[2], B1.x, sA1);
        sB0 = fma2(qh[2], A1.x, sB0);  sB1 = fma2(qh[2], B1.x, sB1);
        sA0 = fma2(qg[3], A1.y, sA0);  sA1 = fma2(qg[3], B1.y, sA1);
        sB0 = fma2(qh[3], A1.y, sB0);  sB1 = fma2(qh[3], B1.y, sB1);
        sA0 = fma2(qg[4], A2.x, sA0);  sA1 = fma2(qg[4], B2.x, sA1);
        sB0 = fma2(qh[4], A2.x, sB0);  sB1 = fma2(qh[4], B2.x, sB1);
        sA0 = fma2(qg[5], A2.y, sA0);  sA1 = fma2(qg[5], B2.y, sA1);
        sB0 = fma2(qh[5], A2.y, sB0);  sB1 = fma2(qh[5], B2.y, sB1);
        sA0 = fma2(qg[6], A3,   sA0);  sA1 = fma2(qg[6], B3,   sA1);
        sB0 = fma2(qh[6], A3,   sB0);  sB1 = fma2(qh[6], B3,   sB1);

        float a0l, a0h, a1l, a1h, a2l, a2h, a3l, a3h;
        unpack2(sA0, a0l, a0h);
        unpack2(sB0, a1l, a1h);
        unpack2(sA1, a2l, a2h);
        unpack2(sB1, a3l, a3h);
        float e0l, e0h, e1l, e1h, e2l, e2h, e3l, e3h;
        asm("ex2.approx.ftz.f32 %0,%1;" : "=f"(e0l) : "f"(a0l));
        asm("ex2.approx.ftz.f32 %0,%1;" : "=f"(e0h) : "f"(a0h));
        asm("ex2.approx.ftz.f32 %0,%1;" : "=f"(e1l) : "f"(a1l));
        asm("ex2.approx.ftz.f32 %0,%1;" : "=f"(e1h) : "f"(a1h));
        asm("ex2.approx.ftz.f32 %0,%1;" : "=f"(e2l) : "f"(a2l));
        asm("ex2.approx.ftz.f32 %0,%1;" : "=f"(e2h) : "f"(a2h));
        asm("ex2.approx.ftz.f32 %0,%1;" : "=f"(e3l) : "f"(a3l));
        asm("ex2.approx.ftz.f32 %0,%1;" : "=f"(e3h) : "f"(a3h));

        u32 fa0 = bf16x2_of(e0l, e0h);   // row g,   k 2tg,2tg+1
        u32 fa1 = bf16x2_of(e1l, e1h);   // row g+8, k 2tg,2tg+1
        u32 fa2 = bf16x2_of(e2l, e2h);   // row g,   k 2tg+8,2tg+9
        u32 fa3 = bf16x2_of(e3l, e3h);   // row g+8, k 2tg+8,2tg+9

        u32 b0, b1;
        asm("ld.shared.v2.u32 {%0,%1}, [%2];"
            : "=r"(b0), "=r"(b1)
            : "r"((u32)__cvta_generic_to_shared(vp)));

        asm("mma.sync.aligned.m16n8k16.row.col.f32.bf16.bf16.f32 "
            "{%0,%1,%2,%3}, {%4,%5,%6,%7}, {%8,%9}, {%0,%1,%2,%3};"
            : "+f"(c0), "+f"(c1), "+f"(c2), "+f"(c3)
            : "r"(fa0), "r"(fa1), "r"(fa2), "r"(fa3), "r"(b0), "r"(b1));

        kp += 512;    // 8 pairs * 64B
        vp += 256;
    }

    // ---- epilogue: C rows g, g+8; cols 2tg, 2tg+1 (col 7 = ssum) ----
    float sg = __shfl_sync(0xffffffffu, c1, lane | 3);
    float sh = __shfl_sync(0xffffffffu, c3, lane | 3);
    float ig = 1.0f / sg;
    float ih = 1.0f / sh;

    float* o0 = out + ((size_t)nh * LEN + qb + g) * DD;
    float* o1 = o0 + 8 * DD;
    if (tg < 3) {
        o0[2 * tg]     = c0 * ig;
        o0[2 * tg + 1] = c1 * ig;
        o1[2 * tg]     = c2 * ih;
        o1[2 * tg + 1] = c3 * ih;
    } else {
        o0[6] = c0 * ig;
        o1[6] = c2 * ih;
    }
}

// ---------------------------------------------------------------------------
extern "C" void kernel_launch(void* const* d_in, const int* in_sizes, int n_in,
                              void* d_out, int out_size)
{
    const float* x  = (const float*)d_in[0];
    const float* Wq = (const float*)d_in[1];
    const float* bq = (const float*)d_in[2];
    const float* Wk = (const float*)d_in[3];
    const float* bk = (const float*)d_in[4];
    const float* Wv = (const float*)d_in[5];
    const float* bv = (const float*)d_in[6];
    float* out = (float*)d_out;

    cudaFuncSetAttribute(proj_kernel, cudaFuncAttributeMaxDynamicSharedMemorySize, PROJ_SMEM);
    cudaFuncSetAttribute(attn_kernel, cudaFuncAttributeMaxDynamicSharedMemorySize, ATTN_SMEM);

    prep_kernel<<<(3 * 56 * SZ + 255) / 256, 256>>>(Wq, Wk, Wv);

    dim3 pgrid((NB * LEN) / PROJ_ROWS, 3);       // 256 x 3
    proj_kernel<<<pgrid, PTHREADS, PROJ_SMEM>>>(x, bq, bk, bv);

    dim3 agrid(NH, 16);                          // 128 x 16 = 2048 CTAs
    attn_kernel<<<agrid, ATHR, ATTN_SMEM>>>(out);
}